// round 2
// baseline (speedup 1.0000x reference)
#include <cuda_runtime.h>
#include <cstdint>

// Problem dims (fixed by reference)
#define BB 256
#define TT 1024
#define DD 64
#define HH 128

typedef unsigned long long ull;

static constexpr size_t BT  = (size_t)BB * TT;        // 262144
static constexpr size_t BTH = (size_t)BB * TT * HH;   // 33554432

// Scratch for precomputed input projections (no cudaMalloc allowed).
// Padded by 4 rows so the scan's software prefetch can load unconditionally.
__device__ float g_gK[BTH + 4 * HH];
__device__ float g_z [BTH + 4 * HH];

// ---- packed f32x2 helpers ----
__device__ __forceinline__ void fma2(ull& acc, ull a, ull b) {
    asm("fma.rn.f32x2 %0, %1, %2, %0;" : "+l"(acc) : "l"(a), "l"(b));
}
__device__ __forceinline__ void add2(ull& a, ull b) {
    asm("add.rn.f32x2 %0, %0, %1;" : "+l"(a) : "l"(b));
}
__device__ __forceinline__ float2 unpk(ull v) {
    float2 f;
    asm("mov.b64 {%0, %1}, %2;" : "=f"(f.x), "=f"(f.y) : "l"(v));
    return f;
}
__device__ __forceinline__ float frcp(float x) {
    float r;
    asm("rcp.approx.f32 %0, %1;" : "=f"(r) : "f"(x));
    return r;
}
// Overflow-safe fast tanh: tanh(x) = sign(x) * (1-e)/(1+e), e = exp(-2|x|)
__device__ __forceinline__ float fast_tanh(float x) {
    float a = fabsf(x);
    float e = __expf(-2.0f * a);
    float t = (1.0f - e) * frcp(1.0f + e);
    return copysignf(t, x);
}
__device__ __forceinline__ float fast_sigmoid(float x) {
    return frcp(1.0f + __expf(-x));
}

// ---------------------------------------------------------------------------
// Kernel 1: input projections. Each CTA: 64 rows of x; thread i = h-index i.
// W_xK[i][:], W_xz[i][:] in registers (f32x2 pairs). 2-row unroll, 8 accums.
// ---------------------------------------------------------------------------
__global__ void __launch_bounds__(128)
proj_kernel(const float* __restrict__ x,
            const float* __restrict__ WxK, const float* __restrict__ bxK,
            const float* __restrict__ Wxz, const float* __restrict__ bxz)
{
    constexpr int ROWS = 64;
    __shared__ __align__(16) float xs[ROWS * DD];   // 16 KB

    const int i = threadIdx.x;                       // h index 0..127
    const size_t row0 = (size_t)blockIdx.x * ROWS;

    // Cooperative load of the x tile (64 rows x 64 floats = 1024 float4)
    const float4* xg  = (const float4*)(x + row0 * DD);
    float4*       xs4 = (float4*)xs;
#pragma unroll
    for (int k = 0; k < 8; k++) xs4[i + 128 * k] = xg[i + 128 * k];

    // W rows into registers: wK[m] holds floats (4m..4m+3) as two f32x2
    ulonglong2 wK[16], wz[16];
    {
        const ulonglong2* wKr = (const ulonglong2*)(WxK + i * DD);
        const ulonglong2* wzr = (const ulonglong2*)(Wxz + i * DD);
#pragma unroll
        for (int m = 0; m < 16; m++) { wK[m] = wKr[m]; wz[m] = wzr[m]; }
    }
    const float bK = bxK[i];
    const float bz = bxz[i];
    __syncthreads();

    for (int r = 0; r < ROWS; r += 2) {
        const ulonglong2* xr0 = (const ulonglong2*)(xs + r * DD);
        const ulonglong2* xr1 = (const ulonglong2*)(xs + (r + 1) * DD);
        ull aK0 = 0, aK1 = 0, az0 = 0, az1 = 0;
        ull cK0 = 0, cK1 = 0, cz0 = 0, cz1 = 0;
#pragma unroll
        for (int m = 0; m < 16; m++) {
            ulonglong2 xv0 = xr0[m];
            ulonglong2 xv1 = xr1[m];
            fma2(aK0, wK[m].x, xv0.x); fma2(aK1, wK[m].y, xv0.y);
            fma2(az0, wz[m].x, xv0.x); fma2(az1, wz[m].y, xv0.y);
            fma2(cK0, wK[m].x, xv1.x); fma2(cK1, wK[m].y, xv1.y);
            fma2(cz0, wz[m].x, xv1.x); fma2(cz1, wz[m].y, xv1.y);
        }
        add2(aK0, aK1); add2(az0, az1); add2(cK0, cK1); add2(cz0, cz1);
        float2 k0 = unpk(aK0), z0 = unpk(az0);
        float2 k1 = unpk(cK0), z1 = unpk(cz0);

        size_t n0 = (row0 + r) * HH + i;
        size_t n1 = n0 + HH;
        g_gK[n0] = k0.x + k0.y + bK;
        g_z [n0] = fast_tanh(z0.x + z0.y + bz);
        g_gK[n1] = k1.x + k1.y + bK;
        g_z [n1] = fast_tanh(z1.x + z1.y + bz);
    }
}

// ---------------------------------------------------------------------------
// Kernel 2: sequential scan. One CTA per batch, thread i = h-index i.
// W_hK row i in 128 registers (f32x2 pairs), 4 accumulators, h double-buffered
// in smem (1 barrier/step), prefetch depth 3 from padded global scratch.
// ---------------------------------------------------------------------------
__global__ void __launch_bounds__(128, 2)
scan_kernel(const float* __restrict__ WhK, const float* __restrict__ bhK,
            float* __restrict__ out, int dup)
{
    __shared__ __align__(16) float hbuf[2][HH];

    const int i = threadIdx.x;
    const int b = blockIdx.x;

    // W_hK row i: w[k] holds floats (4k..4k+3) as two f32x2
    ulonglong2 w[32];
    {
        const ulonglong2* wr = (const ulonglong2*)(WhK + i * HH);
#pragma unroll
        for (int k = 0; k < 32; k++) w[k] = wr[k];
    }
    const float bh = bhK[i];

    hbuf[0][i] = 0.0f;
    float h = 0.0f;

    const float* gp = g_gK + (size_t)b * TT * HH + i;
    const float* zp = g_z  + (size_t)b * TT * HH + i;
    float* op  = out + (size_t)b * TT * HH + i;
    float* op2 = op + BTH;

    // software pipeline depth 3 (arrays are padded; loads are unconditional)
    float g0 = gp[0],      z0v = zp[0];
    float g1 = gp[HH],     z1v = zp[HH];
    float g2 = gp[2 * HH], z2v = zp[2 * HH];
    const float* gp3 = gp + 3 * HH;
    const float* zp3 = zp + 3 * HH;

    __syncthreads();

    int cur = 0;
    for (int t = 0; t < TT; t++) {
        // matvec: ghK_i = sum_j h[j] * W[i][j]
        const ulonglong2* hv = (const ulonglong2*)hbuf[cur];
        ull a0 = 0, a1 = 0, a2 = 0, a3 = 0;
#pragma unroll
        for (int k = 0; k < 32; k += 2) {
            ulonglong2 hA = hv[k];
            ulonglong2 hB = hv[k + 1];
            fma2(a0, w[k].x,     hA.x);
            fma2(a1, w[k].y,     hA.y);
            fma2(a2, w[k + 1].x, hB.x);
            fma2(a3, w[k + 1].y, hB.y);
        }
        add2(a0, a2); add2(a1, a3); add2(a0, a1);
        float2 p = unpk(a0);
        float ghK = p.x + p.y + bh;

        float kg  = fast_sigmoid(g0 + ghK);
        float pre = h + kg * (z0v - h);
        h = fast_tanh(pre);

        // rotate prefetch pipeline
        g0 = g1; z0v = z1v;
        g1 = g2; z1v = z2v;
        g2 = *gp3; z2v = *zp3;
        gp3 += HH; zp3 += HH;

        op[0] = h;
        if (dup) op2[0] = h;
        op += HH; op2 += HH;

        cur ^= 1;
        hbuf[cur][i] = h;
        __syncthreads();
    }
}

// ---------------------------------------------------------------------------
extern "C" void kernel_launch(void* const* d_in, const int* in_sizes, int n_in,
                              void* d_out, int out_size)
{
    const float* x   = (const float*)d_in[0];
    const float* WxK = (const float*)d_in[1];
    const float* bxK = (const float*)d_in[2];
    const float* Wxz = (const float*)d_in[3];
    const float* bxz = (const float*)d_in[4];
    const float* WhK = (const float*)d_in[5];
    const float* bhK = (const float*)d_in[6];
    float* out = (float*)d_out;

    proj_kernel<<<(int)(BT / 64), 128>>>(x, WxK, bxK, Wxz, bxz);

    const int dup = ((size_t)out_size >= 2 * BTH) ? 1 : 0;
    scan_kernel<<<BB, 128>>>(WhK, bhK, out, dup);
}

// round 4
// speedup vs baseline: 1.1807x; 1.1807x over previous
#include <cuda_runtime.h>
#include <cstdint>

// Problem dims (fixed by reference)
#define BB 256
#define TT 1024
#define DD 64
#define HH 128

typedef unsigned long long ull;

static constexpr size_t BT  = (size_t)BB * TT;        // 262144
static constexpr size_t BTH = (size_t)BB * TT * HH;   // 33554432

// Interleaved scratch: (gate_x_K, tanh(gate_x_z)) per (b,t,h). No cudaMalloc allowed.
__device__ float2 g_gz[BTH + 4 * HH];

// ---- packed f32x2 helpers ----
__device__ __forceinline__ void fma2(ull& acc, ull a, ull b) {
    asm("fma.rn.f32x2 %0, %1, %2, %0;" : "+l"(acc) : "l"(a), "l"(b));
}
__device__ __forceinline__ void add2(ull& a, ull b) {
    asm("add.rn.f32x2 %0, %0, %1;" : "+l"(a) : "l"(b));
}
__device__ __forceinline__ float2 unpk(ull v) {
    float2 f;
    asm("mov.b64 {%0, %1}, %2;" : "=f"(f.x), "=f"(f.y) : "l"(v));
    return f;
}
__device__ __forceinline__ float frcp(float x) {
    float r;
    asm("rcp.approx.f32 %0, %1;" : "=f"(r) : "f"(x));
    return r;
}
// Overflow-safe fast tanh: tanh(x) = sign(x) * (1-e)/(1+e), e = exp(-2|x|)
__device__ __forceinline__ float fast_tanh(float x) {
    float a = fabsf(x);
    float e = __expf(-2.0f * a);
    float t = (1.0f - e) * frcp(1.0f + e);
    return copysignf(t, x);
}
__device__ __forceinline__ float fast_sigmoid(float x) {
    return frcp(1.0f + __expf(-x));
}

// ---------------------------------------------------------------------------
// Kernel 1: input projections. Each CTA: 64 rows of x; thread i = h-index i.
// W_xK[i][:], W_xz[i][:] in registers (f32x2 pairs). 2-row unroll, 8 accums.
// Writes interleaved (gK, tanh(gz)) float2.
// ---------------------------------------------------------------------------
__global__ void __launch_bounds__(128)
proj_kernel(const float* __restrict__ x,
            const float* __restrict__ WxK, const float* __restrict__ bxK,
            const float* __restrict__ Wxz, const float* __restrict__ bxz)
{
    constexpr int ROWS = 64;
    __shared__ __align__(16) float xs[ROWS * DD];   // 16 KB

    const int i = threadIdx.x;                       // h index 0..127
    const size_t row0 = (size_t)blockIdx.x * ROWS;

    // Cooperative load of the x tile (64 rows x 64 floats = 1024 float4)
    const float4* xg  = (const float4*)(x + row0 * DD);
    float4*       xs4 = (float4*)xs;
#pragma unroll
    for (int k = 0; k < 8; k++) xs4[i + 128 * k] = xg[i + 128 * k];

    // W rows into registers: wK[m] holds floats (4m..4m+3) as two f32x2
    ulonglong2 wK[16], wz[16];
    {
        const ulonglong2* wKr = (const ulonglong2*)(WxK + i * DD);
        const ulonglong2* wzr = (const ulonglong2*)(Wxz + i * DD);
#pragma unroll
        for (int m = 0; m < 16; m++) { wK[m] = wKr[m]; wz[m] = wzr[m]; }
    }
    const float bK = bxK[i];
    const float bz = bxz[i];
    __syncthreads();

    for (int r = 0; r < ROWS; r += 2) {
        const ulonglong2* xr0 = (const ulonglong2*)(xs + r * DD);
        const ulonglong2* xr1 = (const ulonglong2*)(xs + (r + 1) * DD);
        ull aK0 = 0, aK1 = 0, az0 = 0, az1 = 0;
        ull cK0 = 0, cK1 = 0, cz0 = 0, cz1 = 0;
#pragma unroll
        for (int m = 0; m < 16; m++) {
            ulonglong2 xv0 = xr0[m];
            ulonglong2 xv1 = xr1[m];
            fma2(aK0, wK[m].x, xv0.x); fma2(aK1, wK[m].y, xv0.y);
            fma2(az0, wz[m].x, xv0.x); fma2(az1, wz[m].y, xv0.y);
            fma2(cK0, wK[m].x, xv1.x); fma2(cK1, wK[m].y, xv1.y);
            fma2(cz0, wz[m].x, xv1.x); fma2(cz1, wz[m].y, xv1.y);
        }
        add2(aK0, aK1); add2(az0, az1); add2(cK0, cK1); add2(cz0, cz1);
        float2 k0 = unpk(aK0), z0 = unpk(az0);
        float2 k1 = unpk(cK0), z1 = unpk(cz0);

        size_t n0 = (row0 + r) * HH + i;
        size_t n1 = n0 + HH;
        g_gz[n0] = make_float2(k0.x + k0.y + bK, fast_tanh(z0.x + z0.y + bz));
        g_gz[n1] = make_float2(k1.x + k1.y + bK, fast_tanh(z1.x + z1.y + bz));
    }
}

// ---------------------------------------------------------------------------
// Kernel 2: sequential scan. One CTA (256 threads) per batch.
// Output i is computed by the lane PAIR (2i, 2i+1): even lane dots h[0:64],
// odd lane dots h[64:128] (64 floats each => 32 ull weights, 16 ulonglong2
// shared reads), combined with one shfl.bfly. Both lanes then redundantly
// compute the activation (bitwise identical), so there is exactly ONE
// __syncthreads per step. Even lane stores out + next h; odd stores dup.
// ---------------------------------------------------------------------------
__global__ void __launch_bounds__(256, 2)
scan_kernel(const float* __restrict__ WhK, const float* __restrict__ bhK,
            float* __restrict__ out, int dup)
{
    __shared__ __align__(16) float hbuf[2][HH];

    const int tid  = threadIdx.x;
    const int i    = tid >> 1;        // output index 0..127
    const int half = tid & 1;         // which half of the dot product
    const int b    = blockIdx.x;

    // This lane's 64 weights: W_hK[i][64*half .. 64*half+63] as 32 f32x2
    ull w[32];
    {
        const ull* wr = (const ull*)(WhK + i * HH + half * 64);
#pragma unroll
        for (int k = 0; k < 32; k++) w[k] = wr[k];
    }
    const float bh = bhK[i];

    if (tid < HH) hbuf[0][tid] = 0.0f;
    float h = 0.0f;

    const float2* gp = g_gz + (size_t)b * TT * HH + i;   // pair lanes load same addr
    float* op  = out + (size_t)b * TT * HH + i;
    float* op2 = op + BTH;

    // software pipeline depth 2
    float2 gz0 = gp[0];
    float2 gz1 = gp[HH];

    __syncthreads();

    int cur = 0;
    for (int t = 0; t < TT; t++) {
        // half-dot: sum over 64 h values (16 x LDS.128)
        const ulonglong2* hv = (const ulonglong2*)(hbuf[cur] + half * 64);
        ull a0 = 0, a1 = 0, a2 = 0, a3 = 0;
#pragma unroll
        for (int k = 0; k < 16; k += 2) {
            ulonglong2 hA = hv[k];
            ulonglong2 hB = hv[k + 1];
            fma2(a0, w[2 * k],     hA.x);
            fma2(a1, w[2 * k + 1], hA.y);
            fma2(a2, w[2 * k + 2], hB.x);
            fma2(a3, w[2 * k + 3], hB.y);
        }
        add2(a0, a2); add2(a1, a3); add2(a0, a1);
        float2 p = unpk(a0);
        float s = p.x + p.y;
        s += __shfl_xor_sync(0xFFFFFFFFu, s, 1);   // combine halves (commutative)
        s += bh;

        // both lanes compute identical activation
        float kg = fast_sigmoid(gz0.x + s);
        h = fast_tanh(h + kg * (gz0.y - h));

        // rotate prefetch
        gz0 = gz1;
        if (t + 2 < TT) gz1 = gp[(size_t)(t + 2) * HH];

        if (half == 0) {
            op[(size_t)t * HH] = h;
        } else if (dup) {
            op2[(size_t)t * HH] = h;
        }

        cur ^= 1;
        if (half == 0) hbuf[cur][i] = h;
        __syncthreads();
    }
}

// ---------------------------------------------------------------------------
extern "C" void kernel_launch(void* const* d_in, const int* in_sizes, int n_in,
                              void* d_out, int out_size)
{
    const float* x   = (const float*)d_in[0];
    const float* WxK = (const float*)d_in[1];
    const float* bxK = (const float*)d_in[2];
    const float* Wxz = (const float*)d_in[3];
    const float* bxz = (const float*)d_in[4];
    const float* WhK = (const float*)d_in[5];
    const float* bhK = (const float*)d_in[6];
    float* out = (float*)d_out;

    proj_kernel<<<(int)(BT / 64), 128>>>(x, WxK, bxK, Wxz, bxz);

    const int dup = ((size_t)out_size >= 2 * BTH) ? 1 : 0;
    scan_kernel<<<BB, 256>>>(WhK, bhK, out, dup);
}

// round 5
// speedup vs baseline: 1.2989x; 1.1001x over previous
#include <cuda_runtime.h>
#include <cstdint>

// Problem dims (fixed by reference)
#define BB 256
#define TT 1024
#define DD 64
#define HH 128

typedef unsigned long long ull;

static constexpr size_t BT  = (size_t)BB * TT;        // 262144
static constexpr size_t BTH = (size_t)BB * TT * HH;   // 33554432

// Interleaved scratch: (gate_x_K, tanh(gate_x_z)) per (b,t,h). No cudaMalloc allowed.
__device__ float2 g_gz[BTH + 4 * HH];

// ---- packed f32x2 helpers ----
__device__ __forceinline__ void fma2(ull& acc, ull a, ull b) {
    asm("fma.rn.f32x2 %0, %1, %2, %0;" : "+l"(acc) : "l"(a), "l"(b));
}
__device__ __forceinline__ void add2(ull& a, ull b) {
    asm("add.rn.f32x2 %0, %0, %1;" : "+l"(a) : "l"(b));
}
__device__ __forceinline__ float2 unpk(ull v) {
    float2 f;
    asm("mov.b64 {%0, %1}, %2;" : "=f"(f.x), "=f"(f.y) : "l"(v));
    return f;
}
__device__ __forceinline__ ull pack2(float x, float y) {
    ull r;
    asm("mov.b64 %0, {%1, %2};" : "=l"(r) : "f"(x), "f"(y));
    return r;
}
__device__ __forceinline__ float frcp(float x) {
    float r;
    asm("rcp.approx.f32 %0, %1;" : "=f"(r) : "f"(x));
    return r;
}
// Overflow-safe fast tanh: tanh(x) = sign(x) * (1-e)/(1+e), e = exp(-2|x|)
__device__ __forceinline__ float fast_tanh(float x) {
    float a = fabsf(x);
    float e = __expf(-2.0f * a);
    float t = (1.0f - e) * frcp(1.0f + e);
    return copysignf(t, x);
}
__device__ __forceinline__ float fast_sigmoid(float x) {
    return frcp(1.0f + __expf(-x));
}

// ---------------------------------------------------------------------------
// Kernel 1: input projections. Each CTA: 64 rows of x; thread i = h-index i.
// (unchanged from the round-2 version, which measured ~230us)
// ---------------------------------------------------------------------------
__global__ void __launch_bounds__(128)
proj_kernel(const float* __restrict__ x,
            const float* __restrict__ WxK, const float* __restrict__ bxK,
            const float* __restrict__ Wxz, const float* __restrict__ bxz)
{
    constexpr int ROWS = 64;
    __shared__ __align__(16) float xs[ROWS * DD];   // 16 KB

    const int i = threadIdx.x;                       // h index 0..127
    const size_t row0 = (size_t)blockIdx.x * ROWS;

    const float4* xg  = (const float4*)(x + row0 * DD);
    float4*       xs4 = (float4*)xs;
#pragma unroll
    for (int k = 0; k < 8; k++) xs4[i + 128 * k] = xg[i + 128 * k];

    ulonglong2 wK[16], wz[16];
    {
        const ulonglong2* wKr = (const ulonglong2*)(WxK + i * DD);
        const ulonglong2* wzr = (const ulonglong2*)(Wxz + i * DD);
#pragma unroll
        for (int m = 0; m < 16; m++) { wK[m] = wKr[m]; wz[m] = wzr[m]; }
    }
    const float bK = bxK[i];
    const float bz = bxz[i];
    __syncthreads();

    for (int r = 0; r < ROWS; r += 2) {
        const ulonglong2* xr0 = (const ulonglong2*)(xs + r * DD);
        const ulonglong2* xr1 = (const ulonglong2*)(xs + (r + 1) * DD);
        ull aK0 = 0, aK1 = 0, az0 = 0, az1 = 0;
        ull cK0 = 0, cK1 = 0, cz0 = 0, cz1 = 0;
#pragma unroll
        for (int m = 0; m < 16; m++) {
            ulonglong2 xv0 = xr0[m];
            ulonglong2 xv1 = xr1[m];
            fma2(aK0, wK[m].x, xv0.x); fma2(aK1, wK[m].y, xv0.y);
            fma2(az0, wz[m].x, xv0.x); fma2(az1, wz[m].y, xv0.y);
            fma2(cK0, wK[m].x, xv1.x); fma2(cK1, wK[m].y, xv1.y);
            fma2(cz0, wz[m].x, xv1.x); fma2(cz1, wz[m].y, xv1.y);
        }
        add2(aK0, aK1); add2(az0, az1); add2(cK0, cK1); add2(cz0, cz1);
        float2 k0 = unpk(aK0), z0 = unpk(az0);
        float2 k1 = unpk(cK0), z1 = unpk(cz0);

        size_t n0 = (row0 + r) * HH + i;
        size_t n1 = n0 + HH;
        g_gz[n0] = make_float2(k0.x + k0.y + bK, fast_tanh(z0.x + z0.y + bz));
        g_gz[n1] = make_float2(k1.x + k1.y + bK, fast_tanh(z1.x + z1.y + bz));
    }
}

// ---------------------------------------------------------------------------
// Kernel 2: sequential scan, outer-product/shuffle form. One CTA (128 thr)
// per batch. Thread tid = 32w + l:
//   - OWNS h[tid] in a register across the whole scan.
//   - holds weights W_hK[{l, l+32, l+64, l+96}][32w : 32w+32] as 64 f32x2
//     (packed across the output pairs (l,l+32) and (l+64,l+96)).
// Per step: 32 intra-warp shfl broadcasts of h (no smem for the dot),
// 64 fma2 into 4 accumulators; then a 4-way cross-warp partial reduction via
// 4 STS.32 + one barrier + 4 LDS.32 (double-buffered, conflict-free).
// Shared-memory traffic: 2KB/step/CTA vs 64KB in the streaming design.
// ---------------------------------------------------------------------------
__global__ void __launch_bounds__(128, 2)
scan_kernel(const float* __restrict__ WhK, const float* __restrict__ bhK,
            float* __restrict__ out, int dup)
{
    __shared__ float P[2][4][HH];   // [buf][src warp][output j]  = 4KB

    const int tid = threadIdx.x;
    const int w   = tid >> 5;
    const int l   = tid & 31;
    const int b   = blockIdx.x;

    // Weight block: wo01[j] = (W[l][32w+j], W[l+32][32w+j]),
    //               wo23[j] = (W[l+64][32w+j], W[l+96][32w+j])
    ull wo01[32], wo23[32];
    {
        const float* Wb = WhK + 32 * w;     // column offset for this warp's slice
#pragma unroll
        for (int j = 0; j < 32; j++) {
            wo01[j] = pack2(Wb[(l     ) * HH + j], Wb[(l + 32) * HH + j]);
            wo23[j] = pack2(Wb[(l + 64) * HH + j], Wb[(l + 96) * HH + j]);
        }
    }
    const float bh = bhK[tid];

    const float2* gp = g_gz + (size_t)b * TT * HH + tid;
    float* op  = out + (size_t)b * TT * HH + tid;
    float* op2 = op + BTH;

    float h = 0.0f;                  // this thread's owned h[tid]
    float2 gz0 = gp[0];
    float2 gz1 = gp[HH];

    int cur = 0;
    for (int t = 0; t < TT; t++) {
        // Partial dot over inputs h[32w .. 32w+31] (lane j of this warp owns
        // h[32w+j]); outputs {l, l+32, l+64, l+96}.
        ull a0 = 0, a1 = 0, a2 = 0, a3 = 0;
#pragma unroll
        for (int j = 0; j < 32; j += 2) {
            float hA = __shfl_sync(0xFFFFFFFFu, h, j);
            float hB = __shfl_sync(0xFFFFFFFFu, h, j + 1);
            ull hA2 = pack2(hA, hA);
            ull hB2 = pack2(hB, hB);
            fma2(a0, wo01[j],     hA2);
            fma2(a1, wo23[j],     hA2);
            fma2(a2, wo01[j + 1], hB2);
            fma2(a3, wo23[j + 1], hB2);
        }
        add2(a0, a2); add2(a1, a3);
        float2 p01 = unpk(a0), p23 = unpk(a1);

        // Partials to smem: P[cur][w][l+32k]; bank = l -> conflict-free.
        P[cur][w][l]      = p01.x;
        P[cur][w][l + 32] = p01.y;
        P[cur][w][l + 64] = p23.x;
        P[cur][w][l + 96] = p23.y;
        __syncthreads();

        // Reduce 4 partials for output index tid; banks conflict-free.
        float s = P[cur][0][tid] + P[cur][1][tid]
                + P[cur][2][tid] + P[cur][3][tid] + bh;

        float kg = fast_sigmoid(gz0.x + s);
        h = fast_tanh(h + kg * (gz0.y - h));

        // rotate gate prefetch (distance 2)
        gz0 = gz1;
        if (t + 2 < TT) gz1 = gp[(size_t)(t + 2) * HH];

        op[(size_t)t * HH] = h;
        if (dup) op2[(size_t)t * HH] = h;

        cur ^= 1;
    }
}

// ---------------------------------------------------------------------------
extern "C" void kernel_launch(void* const* d_in, const int* in_sizes, int n_in,
                              void* d_out, int out_size)
{
    const float* x   = (const float*)d_in[0];
    const float* WxK = (const float*)d_in[1];
    const float* bxK = (const float*)d_in[2];
    const float* Wxz = (const float*)d_in[3];
    const float* bxz = (const float*)d_in[4];
    const float* WhK = (const float*)d_in[5];
    const float* bhK = (const float*)d_in[6];
    float* out = (float*)d_out;

    proj_kernel<<<(int)(BT / 64), 128>>>(x, WxK, bxK, Wxz, bxz);

    const int dup = ((size_t)out_size >= 2 * BTH) ? 1 : 0;
    scan_kernel<<<BB, 128>>>(WhK, bhK, out, dup);
}

// round 6
// speedup vs baseline: 1.3502x; 1.0395x over previous
#include <cuda_runtime.h>
#include <cstdint>

// Problem dims (fixed by reference)
#define BB 256
#define TT 1024
#define DD 64
#define HH 128

typedef unsigned long long ull;

static constexpr size_t BT  = (size_t)BB * TT;        // 262144
static constexpr size_t BTH = (size_t)BB * TT * HH;   // 33554432

// Interleaved scratch: (gate_x_K, tanh(gate_x_z)) per (b,t,h). No cudaMalloc allowed.
__device__ float2 g_gz[BTH + 4 * HH];

// ---- packed f32x2 helpers ----
__device__ __forceinline__ void fma2(ull& acc, ull a, ull b) {
    asm("fma.rn.f32x2 %0, %1, %2, %0;" : "+l"(acc) : "l"(a), "l"(b));
}
__device__ __forceinline__ void add2(ull& a, ull b) {
    asm("add.rn.f32x2 %0, %0, %1;" : "+l"(a) : "l"(b));
}
__device__ __forceinline__ float2 unpk(ull v) {
    float2 f;
    asm("mov.b64 {%0, %1}, %2;" : "=f"(f.x), "=f"(f.y) : "l"(v));
    return f;
}
__device__ __forceinline__ float frcp(float x) {
    float r;
    asm("rcp.approx.f32 %0, %1;" : "=f"(r) : "f"(x));
    return r;
}
// Overflow-safe fast tanh: tanh(x) = sign(x) * (1-e)/(1+e), e = exp(-2|x|)
__device__ __forceinline__ float fast_tanh(float x) {
    float a = fabsf(x);
    float e = __expf(-2.0f * a);
    float t = (1.0f - e) * frcp(1.0f + e);
    return copysignf(t, x);
}
__device__ __forceinline__ float fast_sigmoid(float x) {
    return frcp(1.0f + __expf(-x));
}

// ---------------------------------------------------------------------------
// Kernel 1: input projections. Each CTA: 64 rows of x; thread i = h-index i.
// (unchanged; measured ~237us)
// ---------------------------------------------------------------------------
__global__ void __launch_bounds__(128)
proj_kernel(const float* __restrict__ x,
            const float* __restrict__ WxK, const float* __restrict__ bxK,
            const float* __restrict__ Wxz, const float* __restrict__ bxz)
{
    constexpr int ROWS = 64;
    __shared__ __align__(16) float xs[ROWS * DD];   // 16 KB

    const int i = threadIdx.x;                       // h index 0..127
    const size_t row0 = (size_t)blockIdx.x * ROWS;

    const float4* xg  = (const float4*)(x + row0 * DD);
    float4*       xs4 = (float4*)xs;
#pragma unroll
    for (int k = 0; k < 8; k++) xs4[i + 128 * k] = xg[i + 128 * k];

    ulonglong2 wK[16], wz[16];
    {
        const ulonglong2* wKr = (const ulonglong2*)(WxK + i * DD);
        const ulonglong2* wzr = (const ulonglong2*)(Wxz + i * DD);
#pragma unroll
        for (int m = 0; m < 16; m++) { wK[m] = wKr[m]; wz[m] = wzr[m]; }
    }
    const float bK = bxK[i];
    const float bz = bxz[i];
    __syncthreads();

    for (int r = 0; r < ROWS; r += 2) {
        const ulonglong2* xr0 = (const ulonglong2*)(xs + r * DD);
        const ulonglong2* xr1 = (const ulonglong2*)(xs + (r + 1) * DD);
        ull aK0 = 0, aK1 = 0, az0 = 0, az1 = 0;
        ull cK0 = 0, cK1 = 0, cz0 = 0, cz1 = 0;
#pragma unroll
        for (int m = 0; m < 16; m++) {
            ulonglong2 xv0 = xr0[m];
            ulonglong2 xv1 = xr1[m];
            fma2(aK0, wK[m].x, xv0.x); fma2(aK1, wK[m].y, xv0.y);
            fma2(az0, wz[m].x, xv0.x); fma2(az1, wz[m].y, xv0.y);
            fma2(cK0, wK[m].x, xv1.x); fma2(cK1, wK[m].y, xv1.y);
            fma2(cz0, wz[m].x, xv1.x); fma2(cz1, wz[m].y, xv1.y);
        }
        add2(aK0, aK1); add2(az0, az1); add2(cK0, cK1); add2(cz0, cz1);
        float2 k0 = unpk(aK0), z0 = unpk(az0);
        float2 k1 = unpk(cK0), z1 = unpk(cz0);

        size_t n0 = (row0 + r) * HH + i;
        size_t n1 = n0 + HH;
        g_gz[n0] = make_float2(k0.x + k0.y + bK, fast_tanh(z0.x + z0.y + bz));
        g_gz[n1] = make_float2(k1.x + k1.y + bK, fast_tanh(z1.x + z1.y + bz));
    }
}

// ---------------------------------------------------------------------------
// Kernel 2: sequential scan. One CTA (128 thr) per batch. Thread tid = 32w+l:
//   - OWNS h[tid]; stages it in a per-warp smem slot each step.
//   - computes partial dots (over inputs h[32w..32w+31]) for the 4 outputs
//     {l, l+32, l+64, l+96}. Weights packed over INPUTS:
//     wgt[k][m] = (W[l+32k][32w+2m], W[l+32k][32w+2m+1]) so the h operand
//     comes straight from a broadcast LDS.128 — no shuffles, no packing.
//   - partial reduction across the 4 warps via 4 STS.32 + 1 bar + 4 LDS.32
//     (conflict-free, double-buffered).
// ---------------------------------------------------------------------------
__global__ void __launch_bounds__(128, 2)
scan_kernel(const float* __restrict__ WhK, const float* __restrict__ bhK,
            float* __restrict__ out, int dup)
{
    __shared__ __align__(16) float hstage[2][HH];   // [buf][h index]
    __shared__ float P[2][4][HH];                   // [buf][src warp][output]

    const int tid = threadIdx.x;
    const int w   = tid >> 5;
    const int l   = tid & 31;
    const int b   = blockIdx.x;

    // Weights: 4 outputs x 32 inputs = 64 f32x2 regs, packed over inputs.
    ull wgt[4][16];
#pragma unroll
    for (int k = 0; k < 4; k++) {
        const ull* row = (const ull*)(WhK + (l + 32 * k) * HH + 32 * w);
#pragma unroll
        for (int m = 0; m < 16; m++) wgt[k][m] = row[m];
    }
    const float bh = bhK[tid];

    const float2* gp = g_gz + (size_t)b * TT * HH + tid;
    float* op  = out + (size_t)b * TT * HH + tid;
    float* op2 = op + BTH;

    float h = 0.0f;
    hstage[0][tid] = 0.0f;
    float2 gz0 = gp[0];
    float2 gz1 = gp[HH];
    __syncwarp();

    int cur = 0;
    for (int t = 0; t < TT; t++) {
        // Broadcast-read this warp's own 32-h slice (8 x LDS.128, N=1).
        const ulonglong2* hv = (const ulonglong2*)(hstage[cur] + 32 * w);

        ull a0 = 0, a0b = 0, a1 = 0, a1b = 0;
        ull a2 = 0, a2b = 0, a3 = 0, a3b = 0;
#pragma unroll
        for (int m = 0; m < 8; m++) {
            ulonglong2 hx = hv[m];     // (h_{4m},h_{4m+1}) , (h_{4m+2},h_{4m+3})
            fma2(a0,  wgt[0][2 * m],     hx.x);
            fma2(a0b, wgt[0][2 * m + 1], hx.y);
            fma2(a1,  wgt[1][2 * m],     hx.x);
            fma2(a1b, wgt[1][2 * m + 1], hx.y);
            fma2(a2,  wgt[2][2 * m],     hx.x);
            fma2(a2b, wgt[2][2 * m + 1], hx.y);
            fma2(a3,  wgt[3][2 * m],     hx.x);
            fma2(a3b, wgt[3][2 * m + 1], hx.y);
        }
        add2(a0, a0b); add2(a1, a1b); add2(a2, a2b); add2(a3, a3b);
        float2 p0 = unpk(a0), p1 = unpk(a1), p2 = unpk(a2), p3 = unpk(a3);

        // Partials: P[cur][w][l+32k]; all lanes hit bank l -> conflict-free.
        P[cur][w][l]      = p0.x + p0.y;
        P[cur][w][l + 32] = p1.x + p1.y;
        P[cur][w][l + 64] = p2.x + p2.y;
        P[cur][w][l + 96] = p3.x + p3.y;
        __syncthreads();

        // Gather the 4 partials for output tid (conflict-free) and activate.
        float s = P[cur][0][tid] + P[cur][1][tid]
                + P[cur][2][tid] + P[cur][3][tid] + bh;

        float kg = fast_sigmoid(gz0.x + s);
        h = fast_tanh(h + kg * (gz0.y - h));

        // rotate gate prefetch (distance 2)
        gz0 = gz1;
        if (t + 2 < TT) gz1 = gp[(size_t)(t + 2) * HH];

        op[(size_t)t * HH] = h;
        if (dup) op2[(size_t)t * HH] = h;

        cur ^= 1;
        hstage[cur][tid] = h;       // warp-private slice: syncwarp is enough
        __syncwarp();
    }
}

// ---------------------------------------------------------------------------
extern "C" void kernel_launch(void* const* d_in, const int* in_sizes, int n_in,
                              void* d_out, int out_size)
{
    const float* x   = (const float*)d_in[0];
    const float* WxK = (const float*)d_in[1];
    const float* bxK = (const float*)d_in[2];
    const float* Wxz = (const float*)d_in[3];
    const float* bxz = (const float*)d_in[4];
    const float* WhK = (const float*)d_in[5];
    const float* bhK = (const float*)d_in[6];
    float* out = (float*)d_out;

    proj_kernel<<<(int)(BT / 64), 128>>>(x, WxK, bxK, Wxz, bxz);

    const int dup = ((size_t)out_size >= 2 * BTH) ? 1 : 0;
    scan_kernel<<<BB, 128>>>(WhK, bhK, out, dup);
}